// round 1
// baseline (speedup 1.0000x reference)
#include <cuda_runtime.h>
#include <math.h>

// Problem constants (B=4, L=2048, H=8, E=64)
#define BB 4
#define LL 2048
#define HH 8
#define EE 64
#define NBH (BB*HH)           // 32
#define NROWS (NBH*LL)        // 65536
#define SCALEF 0.125f         // 1/sqrt(64)
#define STRIDE_L (HH*EE)      // 512 floats between consecutive l in [B,L,H,E]

// Scratch (device globals — no allocation allowed)
__device__ float g_rowsum[NROWS];
__device__ float g_sigv[NROWS];
__device__ float g_coef[NROWS];
__device__ float g_inv2s2[NROWS];

// ---------------------------------------------------------------------------
// K0: per-row sigma transform.
// sig = 3^(sigmoid(5x)+1e-5) - 1, computed to match fp32 reference rounding:
// pow done in double, rounded to f32, then the cancellation-prone "-1" in f32.
// ---------------------------------------------------------------------------
__global__ void k_sig(const float* __restrict__ sigma) {
    int i = blockIdx.x * 256 + threadIdx.x;
    if (i >= NROWS) return;
    int bh = i >> 11;          // /2048
    int l  = i & 2047;
    int b = bh >> 3, h = bh & 7;
    float x = sigma[((size_t)b * LL + l) * HH + h];
    float s32 = (float)(1.0 / (1.0 + exp(-5.0 * (double)x)));
    float sg  = s32 + 1e-5f;
    float p   = (float)exp((double)sg * 1.0986122886681098);  // 3^sg rounded to f32
    float s   = p - 1.0f;
    g_sigv[i]   = s;
    g_coef[i]   = 1.0f / (2.5066282746310002f * s);  // 1/(sqrt(2pi)*s)
    g_inv2s2[i] = 1.0f / (2.0f * s * s);
}

// ---------------------------------------------------------------------------
// K1: causal softmax denominators.  rowsum[b,h,l] = sum_{j<=l} exp(scale*q.k_j)
// Tiled 128x128 fp32 GEMM, 16x16 threads, 8x8 microtile, E chunked by 32.
// ---------------------------------------------------------------------------
__global__ void __launch_bounds__(256) k_rowsum(const float* __restrict__ Q,
                                                const float* __restrict__ K) {
    __shared__ float Qs[32][132];
    __shared__ float Ks[32][132];
    __shared__ float srow[128];
    int bh = blockIdx.y, b = bh >> 3, h = bh & 7;
    int ti = blockIdx.x, l0 = ti * 128;
    int tid = threadIdx.x, tx = tid & 15, ty = tid >> 4;
    if (tid < 128) srow[tid] = 0.f;

    const float* Qb = Q + ((size_t)b * LL) * STRIDE_L + (size_t)h * EE;
    const float* Kb = K + ((size_t)b * LL) * STRIDE_L + (size_t)h * EE;

    float lsum[8];
#pragma unroll
    for (int r = 0; r < 8; r++) lsum[r] = 0.f;

    for (int tj = 0; tj <= ti; tj++) {
        int j0 = tj * 128;
        float acc[8][8];
#pragma unroll
        for (int r = 0; r < 8; r++)
#pragma unroll
            for (int c = 0; c < 8; c++) acc[r][c] = 0.f;

        for (int ec = 0; ec < 2; ec++) {
            __syncthreads();
            {
                int e = tid & 31, lr = tid >> 5;
#pragma unroll
                for (int it = 0; it < 16; it++) {
                    int l = lr + it * 8;
                    Qs[e][l] = Qb[(size_t)(l0 + l) * STRIDE_L + ec * 32 + e];
                    Ks[e][l] = Kb[(size_t)(j0 + l) * STRIDE_L + ec * 32 + e];
                }
            }
            __syncthreads();
#pragma unroll
            for (int kk = 0; kk < 32; kk++) {
                float a[8], bv[8];
                *(float4*)&a[0]  = *(const float4*)&Qs[kk][ty * 8];
                *(float4*)&a[4]  = *(const float4*)&Qs[kk][ty * 8 + 4];
                *(float4*)&bv[0] = *(const float4*)&Ks[kk][tx * 8];
                *(float4*)&bv[4] = *(const float4*)&Ks[kk][tx * 8 + 4];
#pragma unroll
                for (int r = 0; r < 8; r++)
#pragma unroll
                    for (int c = 0; c < 8; c++) acc[r][c] += a[r] * bv[c];
            }
        }
        if (tj < ti) {
#pragma unroll
            for (int r = 0; r < 8; r++) {
                float s = 0.f;
#pragma unroll
                for (int c = 0; c < 8; c++) s += __expf(SCALEF * acc[r][c]);
                lsum[r] += s;
            }
        } else {  // diagonal tile: mask j > l
#pragma unroll
            for (int r = 0; r < 8; r++) {
                int lr_ = ty * 8 + r;
#pragma unroll
                for (int c = 0; c < 8; c++) {
                    int jr_ = tx * 8 + c;
                    if (jr_ <= lr_) lsum[r] += __expf(SCALEF * acc[r][c]);
                }
            }
        }
    }
    __syncthreads();
#pragma unroll
    for (int r = 0; r < 8; r++) atomicAdd(&srow[ty * 8 + r], lsum[r]);
    __syncthreads();
    if (tid < 128) g_rowsum[(size_t)bh * LL + l0 + tid] = srow[tid];
}

// ---------------------------------------------------------------------------
// K2: recompute scores, write normalized series (causal tiles incl. diagonal).
// ---------------------------------------------------------------------------
__global__ void __launch_bounds__(256) k_series(const float* __restrict__ Q,
                                                const float* __restrict__ K,
                                                float* __restrict__ series) {
    __shared__ float Qs[32][132];
    __shared__ float Ks[32][132];
    int bh = blockIdx.y, b = bh >> 3, h = bh & 7;
    int ti = blockIdx.x, l0 = ti * 128;
    int tid = threadIdx.x, tx = tid & 15, ty = tid >> 4;

    const float* Qb = Q + ((size_t)b * LL) * STRIDE_L + (size_t)h * EE;
    const float* Kb = K + ((size_t)b * LL) * STRIDE_L + (size_t)h * EE;

    float invl[8];
#pragma unroll
    for (int r = 0; r < 8; r++)
        invl[r] = 1.0f / g_rowsum[(size_t)bh * LL + l0 + ty * 8 + r];

    for (int tj = 0; tj <= ti; tj++) {
        int j0 = tj * 128;
        float acc[8][8];
#pragma unroll
        for (int r = 0; r < 8; r++)
#pragma unroll
            for (int c = 0; c < 8; c++) acc[r][c] = 0.f;

        for (int ec = 0; ec < 2; ec++) {
            __syncthreads();
            {
                int e = tid & 31, lr = tid >> 5;
#pragma unroll
                for (int it = 0; it < 16; it++) {
                    int l = lr + it * 8;
                    Qs[e][l] = Qb[(size_t)(l0 + l) * STRIDE_L + ec * 32 + e];
                    Ks[e][l] = Kb[(size_t)(j0 + l) * STRIDE_L + ec * 32 + e];
                }
            }
            __syncthreads();
#pragma unroll
            for (int kk = 0; kk < 32; kk++) {
                float a[8], bv[8];
                *(float4*)&a[0]  = *(const float4*)&Qs[kk][ty * 8];
                *(float4*)&a[4]  = *(const float4*)&Qs[kk][ty * 8 + 4];
                *(float4*)&bv[0] = *(const float4*)&Ks[kk][tx * 8];
                *(float4*)&bv[4] = *(const float4*)&Ks[kk][tx * 8 + 4];
#pragma unroll
                for (int r = 0; r < 8; r++)
#pragma unroll
                    for (int c = 0; c < 8; c++) acc[r][c] += a[r] * bv[c];
            }
        }
        // epilogue: p = exp(scale*s)/rowsum, masked; vectorized stores
#pragma unroll
        for (int r = 0; r < 8; r++) {
            int lr_ = ty * 8 + r;
            int gl  = l0 + lr_;
            float p[8];
#pragma unroll
            for (int c = 0; c < 8; c++) {
                int gj = j0 + tx * 8 + c;
                float e = __expf(SCALEF * acc[r][c]) * invl[r];
                p[c] = (gj <= gl) ? e : 0.f;
            }
            float* dst = series + ((size_t)bh * LL + gl) * LL + j0 + tx * 8;
            *(float4*)&dst[0] = make_float4(p[0], p[1], p[2], p[3]);
            *(float4*)&dst[4] = make_float4(p[4], p[5], p[6], p[7]);
        }
    }
}

// ---------------------------------------------------------------------------
// K4: prior + sig for ALL tiles; series=0 for strictly-upper tiles.
// Store-bound elementwise kernel, float4 stores, 512B/warp.
// ---------------------------------------------------------------------------
__global__ void __launch_bounds__(256) k_prior(float* __restrict__ prior,
                                               float* __restrict__ sig,
                                               float* __restrict__ series) {
    int bh = blockIdx.z;
    int ti = blockIdx.y, tj = blockIdx.x;
    int l0 = ti * 128, j0 = tj * 128;
    bool upper = (tj > ti);
    int tid = threadIdx.x;
    int c4 = (tid & 31) * 4;      // column group (float4)
    int r0 = tid >> 5;            // 0..7
#pragma unroll 4
    for (int it = 0; it < 16; it++) {
        int lr = r0 + it * 8;
        int gl = l0 + lr;
        size_t rowi = (size_t)bh * LL + gl;
        float coef = g_coef[rowi];
        float i2s  = g_inv2s2[rowi];
        float sv   = g_sigv[rowi];
        float p[4];
#pragma unroll
        for (int c = 0; c < 4; c++) {
            int gj = j0 + c4 + c;
            int d  = gl - gj;
            float d2 = (float)(d * d);
            p[c] = coef * __expf(-d2 * i2s);
        }
        size_t idx = rowi * LL + j0 + c4;
        *(float4*)&prior[idx] = make_float4(p[0], p[1], p[2], p[3]);
        *(float4*)&sig[idx]   = make_float4(sv, sv, sv, sv);
        if (upper)
            *(float4*)&series[idx] = make_float4(0.f, 0.f, 0.f, 0.f);
    }
}

// ---------------------------------------------------------------------------
// K3: V[b,l,h,e] = sum_s series[b,h,l,s] * values[b,s,h,e]  (causal tiles only)
// ---------------------------------------------------------------------------
__global__ void __launch_bounds__(256) k_pv(const float* __restrict__ series,
                                            const float* __restrict__ V,
                                            float* __restrict__ out) {
    __shared__ float As[32][132];   // [s][l]
    __shared__ float Bs[32][64];    // [s][e]
    int bh = blockIdx.y, b = bh >> 3, h = bh & 7;
    int ti = blockIdx.x, l0 = ti * 128;
    int tid = threadIdx.x, tx = tid & 15, ty = tid >> 4;

    const float* Sb = series + ((size_t)bh * LL + l0) * LL;

    float acc[8][4];
#pragma unroll
    for (int r = 0; r < 8; r++)
#pragma unroll
        for (int c = 0; c < 4; c++) acc[r][c] = 0.f;

    for (int tj = 0; tj <= ti; tj++) {
        for (int sc = 0; sc < 4; sc++) {
            int s0 = tj * 128 + sc * 32;
            __syncthreads();
            {
                int s = tid & 31, lr = tid >> 5;
#pragma unroll
                for (int it = 0; it < 16; it++) {
                    int l = lr + it * 8;
                    As[s][l] = Sb[(size_t)l * LL + s0 + s];
                }
            }
            {
                int e = tid & 63, sr = tid >> 6;
#pragma unroll
                for (int it = 0; it < 8; it++) {
                    int s = sr + it * 4;
                    Bs[s][e] = V[(((size_t)b * LL + s0 + s) * HH + h) * EE + e];
                }
            }
            __syncthreads();
#pragma unroll
            for (int ss = 0; ss < 32; ss++) {
                float a[8], bv[4];
                *(float4*)&a[0]  = *(const float4*)&As[ss][ty * 8];
                *(float4*)&a[4]  = *(const float4*)&As[ss][ty * 8 + 4];
                *(float4*)&bv[0] = *(const float4*)&Bs[ss][tx * 4];
#pragma unroll
                for (int r = 0; r < 8; r++)
#pragma unroll
                    for (int c = 0; c < 4; c++) acc[r][c] += a[r] * bv[c];
            }
        }
    }
#pragma unroll
    for (int r = 0; r < 8; r++) {
        int gl = l0 + ty * 8 + r;
        float* dst = out + (((size_t)b * LL + gl) * HH + h) * EE + tx * 4;
        *(float4*)dst = make_float4(acc[r][0], acc[r][1], acc[r][2], acc[r][3]);
    }
}

// ---------------------------------------------------------------------------
extern "C" void kernel_launch(void* const* d_in, const int* in_sizes, int n_in,
                              void* d_out, int out_size) {
    const float* Q = (const float*)d_in[0];
    const float* K = (const float*)d_in[1];
    const float* V = (const float*)d_in[2];
    const float* S = (const float*)d_in[3];
    float* out = (float*)d_out;

    float* outV      = out;                                   // [B,L,H,E]
    float* outSeries = outV + (size_t)BB * LL * HH * EE;      // [B,H,L,L]
    float* outPrior  = outSeries + (size_t)NBH * LL * LL;     // [B,H,L,L]
    float* outSig    = outPrior + (size_t)NBH * LL * LL;      // [B,H,L,L]

    k_sig<<<NROWS / 256, 256>>>(S);
    k_rowsum<<<dim3(16, NBH), 256>>>(Q, K);
    k_series<<<dim3(16, NBH), 256>>>(Q, K, outSeries);
    k_prior<<<dim3(16, 16, NBH), 256>>>(outPrior, outSig, outSeries);
    k_pv<<<dim3(16, NBH), 256>>>(outSeries, V, outV);
}